// round 16
// baseline (speedup 1.0000x reference)
#include <cuda_runtime.h>
#include <cuda_fp16.h>
#include <cuda_bf16.h>
#include <math.h>
#include <stdint.h>

#define S_TOT 8196
#define L_PAT 8192
#define H_NUM 8
#define HD 64
#define NUM_CLS 4
#define WIN 32
#define WLEN 65
#define CTX 69
#define GK 512

// scratch
__device__ float g_qkv[3ull * H_NUM * S_TOT * HD];
__device__ float g_clsp[32 * 16 * 66];
__device__ int g_cnt[8];
__device__ float2 g_rtab[(size_t)L_PAT * 32];
__device__ __half g_xf[(size_t)S_TOT * GK];
__device__ __half g_af[(size_t)S_TOT * GK];
__device__ __half g_wqf[1536 * GK];
__device__ __half g_wof[512 * GK];

__constant__ float c_ftbl[16] = {
    1.0f, 0.5623413252f, 0.3162277660f, 0.1778279410f,
    0.1f, 0.05623413252f, 0.03162277660f, 0.01778279410f,
    0.01f, 0.005623413252f, 0.003162277660f, 0.001778279410f,
    0.001f, 0.0005623413252f, 0.0003162277660f, 0.0001778279410f
};

extern __shared__ char dynsm[];

__device__ __forceinline__ uint32_t smem_u32(const void* p) {
    uint32_t a;
    asm("{ .reg .u64 t; cvta.to.shared.u64 t, %1; cvt.u32.u64 %0, t; }" : "=r"(a) : "l"(p));
    return a;
}
__device__ __forceinline__ void ldm_x4(uint32_t* r, uint32_t addr) {
    asm volatile("ldmatrix.sync.aligned.m8n8.x4.shared.b16 {%0,%1,%2,%3}, [%4];"
                 : "=r"(r[0]), "=r"(r[1]), "=r"(r[2]), "=r"(r[3]) : "r"(addr));
}
__device__ __forceinline__ void ldm_x4t(uint32_t* r, uint32_t addr) {
    asm volatile("ldmatrix.sync.aligned.m8n8.x4.trans.shared.b16 {%0,%1,%2,%3}, [%4];"
                 : "=r"(r[0]), "=r"(r[1]), "=r"(r[2]), "=r"(r[3]) : "r"(addr));
}
__device__ __forceinline__ void mma_h(float* c, const uint32_t* a, uint32_t b0, uint32_t b1) {
    asm volatile("mma.sync.aligned.m16n8k16.row.col.f32.f16.f16.f32 "
                 "{%0,%1,%2,%3}, {%4,%5,%6,%7}, {%8,%9}, {%0,%1,%2,%3};"
                 : "+f"(c[0]), "+f"(c[1]), "+f"(c[2]), "+f"(c[3])
                 : "r"(a[0]), "r"(a[1]), "r"(a[2]), "r"(a[3]), "r"(b0), "r"(b1));
}
__device__ __forceinline__ uint32_t packf16(float a, float b) {
    __half2 t = __floats2half2_rn(a, b);
    return *(uint32_t*)&t;
}
__device__ __forceinline__ void cp16(uint32_t dst, const void* src, int sz) {
    asm volatile("cp.async.cg.shared.global [%0], [%1], 16, %2;"
                 :: "r"(dst), "l"(src), "r"(sz));
}
#define CP_COMMIT() asm volatile("cp.async.commit_group;" ::: "memory")
#define CP_WAIT0()  asm volatile("cp.async.wait_group 0;" ::: "memory")

// fast exp on FMA pipe (x <= 0 domain)
__device__ __forceinline__ float fexp(float x) {
    x = fmaxf(x, -80.0f);
    float z = fmaf(x, 1.442695041f, 12582912.0f);
    float n = z - 12582912.0f;
    float f = fmaf(x, 1.442695041f, -n);
    float r = 1.3333558e-3f;
    r = fmaf(r, f, 9.6181291e-3f);
    r = fmaf(r, f, 5.5504109e-2f);
    r = fmaf(r, f, 2.4022651e-1f);
    r = fmaf(r, f, 6.9314718e-1f);
    r = fmaf(r, f, 1.0f);
    return r * __int_as_float(((int)n + 127) << 23);
}

// ---------------------------------------------------------------------------
// prep: fused converts + rope table + counter reset
// ---------------------------------------------------------------------------
#define NB_X  ((S_TOT * GK / 4 + 255) / 256)
#define NB_WQ (1536 * GK / 4 / 256)
#define NB_WO (512 * GK / 4 / 256)
#define NB_RT (L_PAT * 32 / 256)
#define NB_PREP (NB_X + NB_WQ + NB_WO + NB_RT)

__global__ void prep_kernel(const float* __restrict__ x,
                            const float* __restrict__ w_qkv,
                            const float* __restrict__ w_out,
                            const float* __restrict__ coords) {
    int b = blockIdx.x;
    if (b < NB_X) {
        if (b == 0 && threadIdx.x < 8) g_cnt[threadIdx.x] = 0;
        int i = b * 256 + threadIdx.x;
        if (i < S_TOT * GK / 4) {
            float4 v = *(const float4*)(x + (size_t)i * 4);
            *(uint2*)(g_xf + (size_t)i * 4) =
                make_uint2(packf16(v.x, v.y), packf16(v.z, v.w));
        }
        return;
    }
    b -= NB_X;
    if (b < NB_WQ) {
        int i = b * 256 + threadIdx.x;
        float4 v = *(const float4*)(w_qkv + (size_t)i * 4);
        *(uint2*)(g_wqf + (size_t)i * 4) =
            make_uint2(packf16(v.x, v.y), packf16(v.z, v.w));
        return;
    }
    b -= NB_WQ;
    if (b < NB_WO) {
        int i = b * 256 + threadIdx.x;
        float4 v = *(const float4*)(w_out + (size_t)i * 4);
        *(uint2*)(g_wof + (size_t)i * 4) =
            make_uint2(packf16(v.x, v.y), packf16(v.z, v.w));
        return;
    }
    b -= NB_WO;
    {
        int idx = b * 256 + threadIdx.x;
        int l = idx >> 5, p = idx & 31;
        float cx = coords[2 * l + 0];
        float cy = coords[2 * l + 1];
        float freq = c_ftbl[p & 15];
        float coord = ((p < 16) ? cx : cy) * 1e-5f;
        float s, c;
        __sincosf(coord * freq, &s, &c);
        g_rtab[idx] = make_float2(c, s);
    }
}

// ---------------------------------------------------------------------------
// plain fp16 mma.sync GEMM (single pass), cp.async double buffer.
// ---------------------------------------------------------------------------
#define SMS 72
#define TILE_B (128 * SMS * 2)
#define STAGE_B (2 * TILE_B)
#define GEMM_SMEM (2 * STAGE_B)

template<int MODE>
__launch_bounds__(256)
__global__ void gemm_f16(const __half* __restrict__ A,
                         const __half* __restrict__ B,
                         const float* __restrict__ bias,
                         float* __restrict__ C, int M, int Ntot) {
    const int tid = threadIdx.x;
    const int wid = tid >> 5;
    const int lane = tid & 31;
    const int wm = (wid >> 2) * 64;
    const int wn = (wid & 3) * 32;
    const int bm = blockIdx.y * 128;
    const int bn = blockIdx.x * 128;

    float c[4][4][4];
#pragma unroll
    for (int i = 0; i < 4; i++)
#pragma unroll
        for (int j = 0; j < 4; j++)
#pragma unroll
            for (int r = 0; r < 4; r++) c[i][j][r] = 0.f;

    const uint32_t smb = smem_u32(dynsm);
    const int lrow = lane & 15;
    const int lcol = (lane >> 4) * 8;

    auto cp_chunk = [&](int ch, int st) {
        uint32_t sb = smb + st * STAGE_B;
#pragma unroll
        for (int it = 0; it < 8; it++) {
            int idx = tid + it * 256;
            int tile = idx >> 10;
            int slot = idx & 1023;
            int row = slot >> 3;
            int c16 = slot & 7;
            uint32_t dst = sb + tile * TILE_B + row * (SMS * 2) + c16 * 16;
            if (tile == 0) {
                int gr = bm + row;
                cp16(dst, A + (size_t)gr * GK + ch * 64 + c16 * 8, gr < M ? 16 : 0);
            } else {
                cp16(dst, B + (size_t)(bn + row) * GK + ch * 64 + c16 * 8, 16);
            }
        }
        CP_COMMIT();
    };

    cp_chunk(0, 0);

    for (int ch = 0; ch < GK / 64; ch++) {
        int st = ch & 1;
        CP_WAIT0();
        __syncthreads();
        if (ch < GK / 64 - 1) cp_chunk(ch + 1, st ^ 1);

        uint32_t a_b = smb + st * STAGE_B;
        uint32_t b_b = a_b + TILE_B;

#pragma unroll
        for (int kk = 0; kk < 4; kk++) {
            uint32_t af[4][4], bf[2][4];
#pragma unroll
            for (int mt = 0; mt < 4; mt++) {
                uint32_t off = ((wm + mt * 16 + lrow) * SMS + kk * 16 + lcol) * 2;
                ldm_x4(af[mt], a_b + off);
            }
#pragma unroll
            for (int g = 0; g < 2; g++) {
                uint32_t off = ((wn + g * 16 + lrow) * SMS + kk * 16 + lcol) * 2;
                ldm_x4(bf[g], b_b + off);
            }
#pragma unroll
            for (int mt = 0; mt < 4; mt++) {
#pragma unroll
                for (int nt = 0; nt < 4; nt++) {
                    int g = nt >> 1, s = nt & 1;
                    mma_h(c[mt][nt], af[mt], bf[g][s], bf[g][s + 2]);
                }
            }
        }
    }

    const int gid = lane >> 2;
    const int tig = lane & 3;
#pragma unroll
    for (int mt = 0; mt < 4; mt++) {
#pragma unroll
        for (int nt = 0; nt < 4; nt++) {
            int n = bn + wn + nt * 8 + tig * 2;
            float bx = bias[n], by = bias[n + 1];
            int m0 = bm + wm + mt * 16 + gid;
#pragma unroll
            for (int half = 0; half < 2; half++) {
                int m = m0 + half * 8;
                if (m >= M) continue;
                float vx = c[mt][nt][half * 2 + 0] + bx;
                float vy = c[mt][nt][half * 2 + 1] + by;
                if (MODE == 0) {
                    *(float2*)&C[(size_t)m * Ntot + n] = make_float2(vx, vy);
                } else {
                    int sel = n >> 9, h = (n >> 6) & 7, d = n & 63;
                    if (sel < 2 && m >= NUM_CLS) {
                        float2 cs = g_rtab[(size_t)(m - NUM_CLS) * 32 + (d >> 1)];
                        float rx = vx * cs.x - vy * cs.y;
                        float ry = vy * cs.x + vx * cs.y;
                        vx = rx; vy = ry;
                    }
                    *(float2*)&g_qkv[(((size_t)(sel * 8 + h) * S_TOT) + m) * 64 + d] =
                        make_float2(vx, vy);
                }
            }
        }
    }
}

// ---------------------------------------------------------------------------
// Fused patch attention + cls split-K (+ last-block combine).
// blocks [0, 1024): patch; blocks [1024, 1152): cls chunk.
// ---------------------------------------------------------------------------
#define NCHUNK 16
#define CCHUNK 513
#define SCBW 516
#define PATCH_BLKS 1024

#define PST 72
#define SQ_E (64 * PST)
#define SK_E (144 * PST)
#define PATCH_SMEM ((SQ_E + 2 * SK_E) * 2 + 128 * 4 + 128 * 4 + 4 * 16 * 66 * 4)

__device__ void cls_part_body(int bidx) {
    float* sm = (float*)dynsm;
    float* qs = sm;                    // 256
    float* scb = qs + 256;             // 4 * SCBW
    float* red = scb + 4 * SCBW;       // 32
    float* gm = red + 32;              // 4
    float* gs = gm + 4;                // 4
    float* osum = gs + 4;              // 8*4*64

    int h = bidx >> 4;
    int chunk = bidx & 15;
    int k0 = chunk * CCHUNK;
    int k1 = min(S_TOT, k0 + CCHUNK);
    int nk = k1 - k0;
    int tid = threadIdx.x;
    int lane = tid & 31, w = tid >> 5;

    const float* Kb = &g_qkv[(size_t)(8 + h) * S_TOT * 64];
    const float* Vb = &g_qkv[(size_t)(16 + h) * S_TOT * 64];

    {
        int ci = tid >> 6, d = tid & 63;
        qs[tid] = g_qkv[(((size_t)h * S_TOT) + ci) * 64 + d];
    }
    __syncthreads();

    float lmax[4] = {-INFINITY, -INFINITY, -INFINITY, -INFINITY};
    for (int s = tid; s < nk; s += 256) {
        const float4* kr = (const float4*)(Kb + (size_t)(k0 + s) * 64);
        float a[4] = {0.f, 0.f, 0.f, 0.f};
#pragma unroll
        for (int i = 0; i < 16; i++) {
            float4 kv = kr[i];
#pragma unroll
            for (int ci = 0; ci < 4; ci++) {
                float4 qv = *(float4*)&qs[ci * 64 + i * 4];
                a[ci] += kv.x * qv.x + kv.y * qv.y + kv.z * qv.z + kv.w * qv.w;
            }
        }
#pragma unroll
        for (int ci = 0; ci < 4; ci++) {
            float sa = a[ci] * 0.125f;
            scb[ci * SCBW + s] = sa;
            lmax[ci] = fmaxf(lmax[ci], sa);
        }
    }
#pragma unroll
    for (int ci = 0; ci < 4; ci++) {
#pragma unroll
        for (int o = 16; o > 0; o >>= 1)
            lmax[ci] = fmaxf(lmax[ci], __shfl_xor_sync(0xffffffffu, lmax[ci], o));
        if (lane == 0) red[ci * 8 + w] = lmax[ci];
    }
    __syncthreads();
    float gmaxv[4];
#pragma unroll
    for (int ci = 0; ci < 4; ci++) {
        float m = red[ci * 8];
#pragma unroll
        for (int i = 1; i < 8; i++) m = fmaxf(m, red[ci * 8 + i]);
        gmaxv[ci] = m;
    }
    __syncthreads();

    float lsum[4] = {0.f, 0.f, 0.f, 0.f};
    for (int s = tid; s < nk; s += 256) {
#pragma unroll
        for (int ci = 0; ci < 4; ci++) {
            float p = __expf(scb[ci * SCBW + s] - gmaxv[ci]);
            scb[ci * SCBW + s] = p;
            lsum[ci] += p;
        }
    }
#pragma unroll
    for (int ci = 0; ci < 4; ci++) {
#pragma unroll
        for (int o = 16; o > 0; o >>= 1)
            lsum[ci] += __shfl_xor_sync(0xffffffffu, lsum[ci], o);
        if (lane == 0) red[ci * 8 + w] = lsum[ci];
    }
    __syncthreads();
    if (tid < 4) {
        float ssum = 0.f;
#pragma unroll
        for (int i = 0; i < 8; i++) ssum += red[tid * 8 + i];
        gs[tid] = ssum;
        gm[tid] = gmaxv[tid];
    }

    int sl = tid >> 2, dcc = tid & 3, dof = dcc * 16;
    float acc[4][16];
#pragma unroll
    for (int ci = 0; ci < 4; ci++)
#pragma unroll
        for (int dd = 0; dd < 16; dd++) acc[ci][dd] = 0.f;

    for (int s = sl; s < nk; s += 64) {
        float p[4];
#pragma unroll
        for (int ci = 0; ci < 4; ci++) p[ci] = scb[ci * SCBW + s];
        const float* vr = Vb + (size_t)(k0 + s) * 64 + dof;
        float vf[16];
#pragma unroll
        for (int i = 0; i < 4; i++) *(float4*)&vf[i * 4] = *(const float4*)&vr[i * 4];
#pragma unroll
        for (int dd = 0; dd < 16; dd++) {
            float vv = vf[dd];
            acc[0][dd] = fmaf(p[0], vv, acc[0][dd]);
            acc[1][dd] = fmaf(p[1], vv, acc[1][dd]);
            acc[2][dd] = fmaf(p[2], vv, acc[2][dd]);
            acc[3][dd] = fmaf(p[3], vv, acc[3][dd]);
        }
    }
#pragma unroll
    for (int o = 4; o <= 16; o <<= 1)
#pragma unroll
        for (int ci = 0; ci < 4; ci++)
#pragma unroll
            for (int dd = 0; dd < 16; dd++)
                acc[ci][dd] += __shfl_xor_sync(0xffffffffu, acc[ci][dd], o);

    if ((lane & 28) == 0) {
#pragma unroll
        for (int ci = 0; ci < 4; ci++)
#pragma unroll
            for (int dd = 0; dd < 16; dd++)
                osum[(w * 4 + ci) * 64 + dof + dd] = acc[ci][dd];
    }
    __syncthreads();

    {
        int ci = tid >> 6, d = tid & 63;
        float v = 0.f;
#pragma unroll
        for (int i = 0; i < 8; i++) v += osum[(i * 4 + ci) * 64 + d];
        float* dst = &g_clsp[((size_t)(h * 4 + ci) * NCHUNK + chunk) * 66];
        dst[2 + d] = v;
        if (d == 0) { dst[0] = gm[ci]; dst[1] = gs[ci]; }
    }

    // last-block combine
    __threadfence();
    __syncthreads();
    __shared__ int s_old;
    if (tid == 0) s_old = atomicAdd(&g_cnt[h], 1);
    __syncthreads();
    if (s_old == NCHUNK - 1) {
        int ci = tid >> 6, d = tid & 63;
        int hc = h * 4 + ci;
        const float* base = &g_clsp[(size_t)hc * NCHUNK * 66];
        float M = -INFINITY;
#pragma unroll
        for (int c = 0; c < NCHUNK; c++) M = fmaxf(M, base[c * 66]);
        float S = 0.f, A = 0.f;
#pragma unroll
        for (int c = 0; c < NCHUNK; c++) {
            float wgt = __expf(base[c * 66] - M);
            S = fmaf(base[c * 66 + 1], wgt, S);
            A = fmaf(base[c * 66 + 2 + d], wgt, A);
        }
        g_af[(size_t)ci * 512 + h * 64 + d] = __float2half(A / S);
    }
}

__launch_bounds__(256)
__global__ void patch_cls_kernel() {
    int blk = blockIdx.x;
    if (blk >= PATCH_BLKS) {
        cls_part_body(blk - PATCH_BLKS);
        return;
    }

    __half* sQ = (__half*)dynsm;
    __half* sK = sQ + SQ_E;
    __half* sV = sK + SK_E;
    float* hm = (float*)(dynsm + (SQ_E + 2 * SK_E) * 2);
    float* hs = hm + 128;
    float* redb = hs + 128;

    int h = blk >> 7;
    int l0 = (blk & 127) * 64;
    int tid = threadIdx.x;

    const float* Qb = &g_qkv[(size_t)h * S_TOT * 64];
    const float* Kb = &g_qkv[(size_t)(8 + h) * S_TOT * 64];
    const float* Vb = &g_qkv[(size_t)(16 + h) * S_TOT * 64];

    for (int i = tid; i < 64 * 8; i += 256) {
        int r = i >> 3, c8 = (i & 7) * 8;
        const float* src = &Qb[(size_t)(NUM_CLS + l0 + r) * 64 + c8];
        float4 a = *(const float4*)src;
        float4 b = *(const float4*)(src + 4);
        uint4 pk = make_uint4(packf16(a.x * 0.125f, a.y * 0.125f),
                              packf16(a.z * 0.125f, a.w * 0.125f),
                              packf16(b.x * 0.125f, b.y * 0.125f),
                              packf16(b.z * 0.125f, b.w * 0.125f));
        *(uint4*)&sQ[r * PST + c8] = pk;
    }
    for (int i = tid; i < 144 * 8; i += 256) {
        int r = i >> 3, c8 = (i & 7) * 8;
        float4 ka = make_float4(0.f, 0.f, 0.f, 0.f), kb = ka, va = ka, vb = ka;
        if (r < 128) {
            int kp = l0 - WIN + r;
            if (kp >= 0 && kp < L_PAT) {
                const float* ks = &Kb[(size_t)(NUM_CLS + kp) * 64 + c8];
                const float* vs = &Vb[(size_t)(NUM_CLS + kp) * 64 + c8];
                ka = *(const float4*)ks; kb = *(const float4*)(ks + 4);
                va = *(const float4*)vs; vb = *(const float4*)(vs + 4);
            }
        } else if (r < 132) {
            const float* ks = &Kb[(size_t)(r - 128) * 64 + c8];
            const float* vs = &Vb[(size_t)(r - 128) * 64 + c8];
            ka = *(const float4*)ks; kb = *(const float4*)(ks + 4);
            va = *(const float4*)vs; vb = *(const float4*)(vs + 4);
        }
        *(uint4*)&sK[r * PST + c8] = make_uint4(packf16(ka.x, ka.y), packf16(ka.z, ka.w),
                                                packf16(kb.x, kb.y), packf16(kb.z, kb.w));
        *(uint4*)&sV[r * PST + c8] = make_uint4(packf16(va.x, va.y), packf16(va.z, va.w),
                                                packf16(vb.x, vb.y), packf16(vb.z, vb.w));
    }
    __syncthreads();

    const int wid = tid >> 5;
    const int lane = tid & 31;
    const int wm = (wid >> 1) * 16;
    const int wh = wid & 1;
    const int lrow = lane & 15;
    const int lcol = (lane >> 4) * 8;
    const int gid = lane >> 2;
    const int tig = lane & 3;

    const uint32_t sQb = smem_u32(sQ);
    const uint32_t sKb = smem_u32(sK);
    const uint32_t sVb = smem_u32(sV);

    int rbase[3];
#pragma unroll
    for (int ti = 0; ti < 3; ti++) {
        int t = wh * 3 + ti;
        rbase[ti] = (t < 5) ? (wm + t * 16) : 128;
    }

    float sf[3][2][4];
#pragma unroll
    for (int g = 0; g < 3; g++)
#pragma unroll
        for (int s = 0; s < 2; s++)
#pragma unroll
            for (int r = 0; r < 4; r++) sf[g][s][r] = 0.f;

#pragma unroll
    for (int kt = 0; kt < 4; kt++) {
        uint32_t af[4];
        ldm_x4(af, sQb + ((wm + lrow) * PST + kt * 16 + lcol) * 2);
#pragma unroll
        for (int g = 0; g < 3; g++) {
            uint32_t bf[4];
            ldm_x4(bf, sKb + ((rbase[g] + lrow) * PST + kt * 16 + lcol) * 2);
            mma_h(sf[g][0], af, bf[0], bf[2]);
            mma_h(sf[g][1], af, bf[1], bf[3]);
        }
    }

    const int row0 = wm + gid;
    const int row1 = row0 + 8;
    float mx0 = -INFINITY, mx1 = -INFINITY;
#pragma unroll
    for (int g = 0; g < 3; g++) {
        int t = wh * 3 + g;
#pragma unroll
        for (int s = 0; s < 2; s++)
#pragma unroll
            for (int j = 0; j < 2; j++) {
                int cc = s * 8 + tig * 2 + j;
                bool v0, v1;
                if (t < 5) {
                    int r = wm + t * 16 + cc;
                    int pos = l0 - WIN + r;
                    bool bok = (pos >= 0) && (pos < L_PAT);
                    v0 = bok && (r >= row0) && (r <= row0 + 64);
                    v1 = bok && (r >= row1) && (r <= row1 + 64);
                } else {
                    v0 = v1 = (cc < 4);
                }
                float a0 = v0 ? sf[g][s][j] : -1e30f;
                float a1 = v1 ? sf[g][s][j + 2] : -1e30f;
                sf[g][s][j] = a0;
                sf[g][s][j + 2] = a1;
                mx0 = fmaxf(mx0, a0);
                mx1 = fmaxf(mx1, a1);
            }
    }
    mx0 = fmaxf(mx0, __shfl_xor_sync(0xffffffffu, mx0, 1));
    mx0 = fmaxf(mx0, __shfl_xor_sync(0xffffffffu, mx0, 2));
    mx1 = fmaxf(mx1, __shfl_xor_sync(0xffffffffu, mx1, 1));
    mx1 = fmaxf(mx1, __shfl_xor_sync(0xffffffffu, mx1, 2));
    if (tig == 0) {
        hm[row0 * 2 + wh] = mx0;
        hm[row1 * 2 + wh] = mx1;
    }
    __syncthreads();
    float M0 = fmaxf(hm[row0 * 2], hm[row0 * 2 + 1]);
    float M1 = fmaxf(hm[row1 * 2], hm[row1 * 2 + 1]);

    float sum0 = 0.f, sum1 = 0.f;
#pragma unroll
    for (int g = 0; g < 3; g++)
#pragma unroll
        for (int s = 0; s < 2; s++) {
            float p0 = fexp(sf[g][s][0] - M0);
            float p1 = fexp(sf[g][s][1] - M0);
            float p2 = fexp(sf[g][s][2] - M1);
            float p3 = fexp(sf[g][s][3] - M1);
            sf[g][s][0] = p0; sf[g][s][1] = p1;
            sf[g][s][2] = p2; sf[g][s][3] = p3;
            sum0 += p0 + p1;
            sum1 += p2 + p3;
        }
    sum0 += __shfl_xor_sync(0xffffffffu, sum0, 1);
    sum0 += __shfl_xor_sync(0xffffffffu, sum0, 2);
    sum1 += __shfl_xor_sync(0xffffffffu, sum1, 1);
    sum1 += __shfl_xor_sync(0xffffffffu, sum1, 2);
    if (tig == 0) {
        hs[row0 * 2 + wh] = sum0;
        hs[row1 * 2 + wh] = sum1;
    }
    __syncthreads();
    float inv0 = 1.0f / (hs[row0 * 2] + hs[row0 * 2 + 1]);
    float inv1 = 1.0f / (hs[row1 * 2] + hs[row1 * 2 + 1]);

    uint32_t PhA[3][4];
#pragma unroll
    for (int kt = 0; kt < 3; kt++) {
#pragma unroll
        for (int s = 0; s < 2; s++) {
            PhA[kt][0 + s * 2] = packf16(sf[kt][s][0] * inv0, sf[kt][s][1] * inv0);
            PhA[kt][1 + s * 2] = packf16(sf[kt][s][2] * inv1, sf[kt][s][3] * inv1);
        }
    }

    float of[8][4];
#pragma unroll
    for (int i = 0; i < 8; i++)
#pragma unroll
        for (int r = 0; r < 4; r++) of[i][r] = 0.f;

#pragma unroll
    for (int dt2 = 0; dt2 < 4; dt2++) {
#pragma unroll
        for (int kt = 0; kt < 3; kt++) {
            uint32_t vb[4];
            ldm_x4t(vb, sVb + ((rbase[kt] + lrow) * PST + dt2 * 16 + lcol) * 2);
            mma_h(of[2 * dt2 + 0], PhA[kt], vb[0], vb[1]);
            mma_h(of[2 * dt2 + 1], PhA[kt], vb[2], vb[3]);
        }
    }

    float* rb = redb + (wm >> 4) * 16 * 66;
    if (wh == 1) {
#pragma unroll
        for (int dt = 0; dt < 8; dt++) {
            int d = dt * 8 + tig * 2;
            *(float2*)&rb[gid * 66 + d] = make_float2(of[dt][0], of[dt][1]);
            *(float2*)&rb[(gid + 8) * 66 + d] = make_float2(of[dt][2], of[dt][3]);
        }
    }
    __syncthreads();
    if (wh == 0) {
#pragma unroll
        for (int dt = 0; dt < 8; dt++) {
            int d = dt * 8 + tig * 2;
            float2 r0 = *(float2*)&rb[gid * 66 + d];
            float2 r1 = *(float2*)&rb[(gid + 8) * 66 + d];
            int grow0 = NUM_CLS + l0 + row0;
            int grow1 = NUM_CLS + l0 + row1;
            *(uint32_t*)&g_af[(size_t)grow0 * 512 + h * 64 + d] =
                packf16(of[dt][0] + r0.x, of[dt][1] + r0.y);
            *(uint32_t*)&g_af[(size_t)grow1 * 512 + h * 64 + d] =
                packf16(of[dt][2] + r1.x, of[dt][3] + r1.y);
        }
    }
}

// ---------------------------------------------------------------------------
extern "C" void kernel_launch(void* const* d_in, const int* in_sizes, int n_in,
                              void* d_out, int out_size) {
    const float* x      = (const float*)d_in[0];
    const float* coords = (const float*)d_in[1];
    const float* w_qkv  = (const float*)d_in[2];
    const float* b_qkv  = (const float*)d_in[3];
    const float* w_out  = (const float*)d_in[4];
    const float* b_out  = (const float*)d_in[5];
    float* out = (float*)d_out;

    __half *xf, *af, *wqf, *wof;
    cudaGetSymbolAddress((void**)&xf, g_xf);
    cudaGetSymbolAddress((void**)&af, g_af);
    cudaGetSymbolAddress((void**)&wqf, g_wqf);
    cudaGetSymbolAddress((void**)&wof, g_wof);

    cudaFuncSetAttribute(gemm_f16<0>, cudaFuncAttributeMaxDynamicSharedMemorySize, GEMM_SMEM);
    cudaFuncSetAttribute(gemm_f16<1>, cudaFuncAttributeMaxDynamicSharedMemorySize, GEMM_SMEM);
    cudaFuncSetAttribute(patch_cls_kernel, cudaFuncAttributeMaxDynamicSharedMemorySize, PATCH_SMEM);

    // 1. fused prep
    prep_kernel<<<NB_PREP, 256>>>(x, w_qkv, w_out, coords);

    // 2. QKV GEMM (rope fused) -> g_qkv scatter
    {
        dim3 grid(1536 / 128, (S_TOT + 127) / 128);
        gemm_f16<1><<<grid, 256, GEMM_SMEM>>>(xf, wqf, b_qkv, nullptr, S_TOT, 0);
    }
    // 3. fused patch + cls (+ last-block combine)
    patch_cls_kernel<<<PATCH_BLKS + 8 * NCHUNK, 256, PATCH_SMEM>>>();

    // 4. out projection
    {
        dim3 grid(512 / 128, (S_TOT + 127) / 128);
        gemm_f16<0><<<grid, 256, GEMM_SMEM>>>(af, wof, b_out, out, S_TOT, 512);
    }
}

// round 17
// speedup vs baseline: 1.0606x; 1.0606x over previous
#include <cuda_runtime.h>
#include <cuda_fp16.h>
#include <cuda_bf16.h>
#include <math.h>
#include <stdint.h>

#define S_TOT 8196
#define L_PAT 8192
#define H_NUM 8
#define HD 64
#define NUM_CLS 4
#define WIN 32
#define WLEN 65
#define CTX 69
#define GK 512

// scratch
__device__ float g_qkv[3ull * H_NUM * S_TOT * HD];
__device__ float g_clsp[32 * 16 * 66];
__device__ int g_cnt[8];
__device__ float2 g_rtab[(size_t)L_PAT * 32];
__device__ __half g_xf[(size_t)S_TOT * GK];
__device__ __half g_af[(size_t)S_TOT * GK];
__device__ __half g_wqf[1536 * GK];
__device__ __half g_wof[512 * GK];

__constant__ float c_ftbl[16] = {
    1.0f, 0.5623413252f, 0.3162277660f, 0.1778279410f,
    0.1f, 0.05623413252f, 0.03162277660f, 0.01778279410f,
    0.01f, 0.005623413252f, 0.003162277660f, 0.001778279410f,
    0.001f, 0.0005623413252f, 0.0003162277660f, 0.0001778279410f
};

extern __shared__ char dynsm[];

__device__ __forceinline__ uint32_t smem_u32(const void* p) {
    uint32_t a;
    asm("{ .reg .u64 t; cvta.to.shared.u64 t, %1; cvt.u32.u64 %0, t; }" : "=r"(a) : "l"(p));
    return a;
}
__device__ __forceinline__ void ldm_x4(uint32_t* r, uint32_t addr) {
    asm volatile("ldmatrix.sync.aligned.m8n8.x4.shared.b16 {%0,%1,%2,%3}, [%4];"
                 : "=r"(r[0]), "=r"(r[1]), "=r"(r[2]), "=r"(r[3]) : "r"(addr));
}
__device__ __forceinline__ void ldm_x4t(uint32_t* r, uint32_t addr) {
    asm volatile("ldmatrix.sync.aligned.m8n8.x4.trans.shared.b16 {%0,%1,%2,%3}, [%4];"
                 : "=r"(r[0]), "=r"(r[1]), "=r"(r[2]), "=r"(r[3]) : "r"(addr));
}
__device__ __forceinline__ void mma_h(float* c, const uint32_t* a, uint32_t b0, uint32_t b1) {
    asm volatile("mma.sync.aligned.m16n8k16.row.col.f32.f16.f16.f32 "
                 "{%0,%1,%2,%3}, {%4,%5,%6,%7}, {%8,%9}, {%0,%1,%2,%3};"
                 : "+f"(c[0]), "+f"(c[1]), "+f"(c[2]), "+f"(c[3])
                 : "r"(a[0]), "r"(a[1]), "r"(a[2]), "r"(a[3]), "r"(b0), "r"(b1));
}
__device__ __forceinline__ uint32_t packf16(float a, float b) {
    __half2 t = __floats2half2_rn(a, b);
    return *(uint32_t*)&t;
}
__device__ __forceinline__ void cp16(uint32_t dst, const void* src, int sz) {
    asm volatile("cp.async.cg.shared.global [%0], [%1], 16, %2;"
                 :: "r"(dst), "l"(src), "r"(sz));
}
#define CP_COMMIT() asm volatile("cp.async.commit_group;" ::: "memory")
#define CP_WAIT0()  asm volatile("cp.async.wait_group 0;" ::: "memory")

// fast exp on FMA pipe (x <= 0 domain)
__device__ __forceinline__ float fexp(float x) {
    x = fmaxf(x, -80.0f);
    float z = fmaf(x, 1.442695041f, 12582912.0f);
    float n = z - 12582912.0f;
    float f = fmaf(x, 1.442695041f, -n);
    float r = 1.3333558e-3f;
    r = fmaf(r, f, 9.6181291e-3f);
    r = fmaf(r, f, 5.5504109e-2f);
    r = fmaf(r, f, 2.4022651e-1f);
    r = fmaf(r, f, 6.9314718e-1f);
    r = fmaf(r, f, 1.0f);
    return r * __int_as_float(((int)n + 127) << 23);
}

// ---------------------------------------------------------------------------
// prep: fused converts + rope table + counter reset
// ---------------------------------------------------------------------------
#define NB_X  ((S_TOT * GK / 4 + 255) / 256)
#define NB_WQ (1536 * GK / 4 / 256)
#define NB_WO (512 * GK / 4 / 256)
#define NB_RT (L_PAT * 32 / 256)
#define NB_PREP (NB_X + NB_WQ + NB_WO + NB_RT)

__global__ void prep_kernel(const float* __restrict__ x,
                            const float* __restrict__ w_qkv,
                            const float* __restrict__ w_out,
                            const float* __restrict__ coords) {
    int b = blockIdx.x;
    if (b < NB_X) {
        if (b == 0 && threadIdx.x < 8) g_cnt[threadIdx.x] = 0;
        int i = b * 256 + threadIdx.x;
        if (i < S_TOT * GK / 4) {
            float4 v = *(const float4*)(x + (size_t)i * 4);
            *(uint2*)(g_xf + (size_t)i * 4) =
                make_uint2(packf16(v.x, v.y), packf16(v.z, v.w));
        }
        return;
    }
    b -= NB_X;
    if (b < NB_WQ) {
        int i = b * 256 + threadIdx.x;
        float4 v = *(const float4*)(w_qkv + (size_t)i * 4);
        *(uint2*)(g_wqf + (size_t)i * 4) =
            make_uint2(packf16(v.x, v.y), packf16(v.z, v.w));
        return;
    }
    b -= NB_WQ;
    if (b < NB_WO) {
        int i = b * 256 + threadIdx.x;
        float4 v = *(const float4*)(w_out + (size_t)i * 4);
        *(uint2*)(g_wof + (size_t)i * 4) =
            make_uint2(packf16(v.x, v.y), packf16(v.z, v.w));
        return;
    }
    b -= NB_WO;
    {
        int idx = b * 256 + threadIdx.x;
        int l = idx >> 5, p = idx & 31;
        float cx = coords[2 * l + 0];
        float cy = coords[2 * l + 1];
        float freq = c_ftbl[p & 15];
        float coord = ((p < 16) ? cx : cy) * 1e-5f;
        float s, c;
        __sincosf(coord * freq, &s, &c);
        g_rtab[idx] = make_float2(c, s);
    }
}

// ---------------------------------------------------------------------------
// plain fp16 mma.sync GEMM (single pass), cp.async double buffer.
// ---------------------------------------------------------------------------
#define SMS 72
#define TILE_B (128 * SMS * 2)
#define STAGE_B (2 * TILE_B)
#define GEMM_SMEM (2 * STAGE_B)

template<int MODE>
__launch_bounds__(256)
__global__ void gemm_f16(const __half* __restrict__ A,
                         const __half* __restrict__ B,
                         const float* __restrict__ bias,
                         float* __restrict__ C, int M, int Ntot) {
    const int tid = threadIdx.x;
    const int wid = tid >> 5;
    const int lane = tid & 31;
    const int wm = (wid >> 2) * 64;
    const int wn = (wid & 3) * 32;
    const int bm = blockIdx.y * 128;
    const int bn = blockIdx.x * 128;

    float c[4][4][4];
#pragma unroll
    for (int i = 0; i < 4; i++)
#pragma unroll
        for (int j = 0; j < 4; j++)
#pragma unroll
            for (int r = 0; r < 4; r++) c[i][j][r] = 0.f;

    const uint32_t smb = smem_u32(dynsm);
    const int lrow = lane & 15;
    const int lcol = (lane >> 4) * 8;

    auto cp_chunk = [&](int ch, int st) {
        uint32_t sb = smb + st * STAGE_B;
#pragma unroll
        for (int it = 0; it < 8; it++) {
            int idx = tid + it * 256;
            int tile = idx >> 10;
            int slot = idx & 1023;
            int row = slot >> 3;
            int c16 = slot & 7;
            uint32_t dst = sb + tile * TILE_B + row * (SMS * 2) + c16 * 16;
            if (tile == 0) {
                int gr = bm + row;
                cp16(dst, A + (size_t)gr * GK + ch * 64 + c16 * 8, gr < M ? 16 : 0);
            } else {
                cp16(dst, B + (size_t)(bn + row) * GK + ch * 64 + c16 * 8, 16);
            }
        }
        CP_COMMIT();
    };

    cp_chunk(0, 0);

    for (int ch = 0; ch < GK / 64; ch++) {
        int st = ch & 1;
        CP_WAIT0();
        __syncthreads();
        if (ch < GK / 64 - 1) cp_chunk(ch + 1, st ^ 1);

        uint32_t a_b = smb + st * STAGE_B;
        uint32_t b_b = a_b + TILE_B;

#pragma unroll
        for (int kk = 0; kk < 4; kk++) {
            uint32_t af[4][4], bf[2][4];
#pragma unroll
            for (int mt = 0; mt < 4; mt++) {
                uint32_t off = ((wm + mt * 16 + lrow) * SMS + kk * 16 + lcol) * 2;
                ldm_x4(af[mt], a_b + off);
            }
#pragma unroll
            for (int g = 0; g < 2; g++) {
                uint32_t off = ((wn + g * 16 + lrow) * SMS + kk * 16 + lcol) * 2;
                ldm_x4(bf[g], b_b + off);
            }
#pragma unroll
            for (int mt = 0; mt < 4; mt++) {
#pragma unroll
                for (int nt = 0; nt < 4; nt++) {
                    int g = nt >> 1, s = nt & 1;
                    mma_h(c[mt][nt], af[mt], bf[g][s], bf[g][s + 2]);
                }
            }
        }
    }

    const int gid = lane >> 2;
    const int tig = lane & 3;
#pragma unroll
    for (int mt = 0; mt < 4; mt++) {
#pragma unroll
        for (int nt = 0; nt < 4; nt++) {
            int n = bn + wn + nt * 8 + tig * 2;
            float bx = bias[n], by = bias[n + 1];
            int m0 = bm + wm + mt * 16 + gid;
#pragma unroll
            for (int half = 0; half < 2; half++) {
                int m = m0 + half * 8;
                if (m >= M) continue;
                float vx = c[mt][nt][half * 2 + 0] + bx;
                float vy = c[mt][nt][half * 2 + 1] + by;
                if (MODE == 0) {
                    *(float2*)&C[(size_t)m * Ntot + n] = make_float2(vx, vy);
                } else {
                    int sel = n >> 9, h = (n >> 6) & 7, d = n & 63;
                    if (sel < 2 && m >= NUM_CLS) {
                        float2 cs = g_rtab[(size_t)(m - NUM_CLS) * 32 + (d >> 1)];
                        float rx = vx * cs.x - vy * cs.y;
                        float ry = vy * cs.x + vx * cs.y;
                        vx = rx; vy = ry;
                    }
                    *(float2*)&g_qkv[(((size_t)(sel * 8 + h) * S_TOT) + m) * 64 + d] =
                        make_float2(vx, vy);
                }
            }
        }
    }
}

// ---------------------------------------------------------------------------
// CLS attention split-K (16 chunks) with fused last-block combine
// ---------------------------------------------------------------------------
#define NCHUNK 16
#define CCHUNK 513
#define SCBW 516

__launch_bounds__(256)
__global__ void cls_part_kernel() {
    __shared__ float qs[4 * 64];
    __shared__ float scb[4 * SCBW];
    __shared__ float red[4][8];
    __shared__ float gm[4], gs[4];
    __shared__ float osum[8][4][64];
    __shared__ int s_old;

    int h = blockIdx.x;
    int chunk = blockIdx.y;
    int k0 = chunk * CCHUNK;
    int k1 = min(S_TOT, k0 + CCHUNK);
    int nk = k1 - k0;
    int tid = threadIdx.x;
    int lane = tid & 31, w = tid >> 5;

    const float* Kb = &g_qkv[(size_t)(8 + h) * S_TOT * 64];
    const float* Vb = &g_qkv[(size_t)(16 + h) * S_TOT * 64];

    {
        int ci = tid >> 6, d = tid & 63;
        qs[tid] = g_qkv[(((size_t)h * S_TOT) + ci) * 64 + d];
    }
    __syncthreads();

    float lmax[4] = {-INFINITY, -INFINITY, -INFINITY, -INFINITY};
    for (int s = tid; s < nk; s += 256) {
        const float4* kr = (const float4*)(Kb + (size_t)(k0 + s) * 64);
        float a[4] = {0.f, 0.f, 0.f, 0.f};
#pragma unroll
        for (int i = 0; i < 16; i++) {
            float4 kv = kr[i];
#pragma unroll
            for (int ci = 0; ci < 4; ci++) {
                float4 qv = *(float4*)&qs[ci * 64 + i * 4];
                a[ci] += kv.x * qv.x + kv.y * qv.y + kv.z * qv.z + kv.w * qv.w;
            }
        }
#pragma unroll
        for (int ci = 0; ci < 4; ci++) {
            float sa = a[ci] * 0.125f;
            scb[ci * SCBW + s] = sa;
            lmax[ci] = fmaxf(lmax[ci], sa);
        }
    }
#pragma unroll
    for (int ci = 0; ci < 4; ci++) {
#pragma unroll
        for (int o = 16; o > 0; o >>= 1)
            lmax[ci] = fmaxf(lmax[ci], __shfl_xor_sync(0xffffffffu, lmax[ci], o));
        if (lane == 0) red[ci][w] = lmax[ci];
    }
    __syncthreads();
    float gmaxv[4];
#pragma unroll
    for (int ci = 0; ci < 4; ci++) {
        float m = red[ci][0];
#pragma unroll
        for (int i = 1; i < 8; i++) m = fmaxf(m, red[ci][i]);
        gmaxv[ci] = m;
    }
    __syncthreads();

    float lsum[4] = {0.f, 0.f, 0.f, 0.f};
    for (int s = tid; s < nk; s += 256) {
#pragma unroll
        for (int ci = 0; ci < 4; ci++) {
            float p = __expf(scb[ci * SCBW + s] - gmaxv[ci]);
            scb[ci * SCBW + s] = p;
            lsum[ci] += p;
        }
    }
#pragma unroll
    for (int ci = 0; ci < 4; ci++) {
#pragma unroll
        for (int o = 16; o > 0; o >>= 1)
            lsum[ci] += __shfl_xor_sync(0xffffffffu, lsum[ci], o);
        if (lane == 0) red[ci][w] = lsum[ci];
    }
    __syncthreads();
    if (tid < 4) {
        float ssum = 0.f;
#pragma unroll
        for (int i = 0; i < 8; i++) ssum += red[tid][i];
        gs[tid] = ssum;
        gm[tid] = gmaxv[tid];
    }

    int sl = tid >> 2, dcc = tid & 3, dof = dcc * 16;
    float acc[4][16];
#pragma unroll
    for (int ci = 0; ci < 4; ci++)
#pragma unroll
        for (int dd = 0; dd < 16; dd++) acc[ci][dd] = 0.f;

    for (int s = sl; s < nk; s += 64) {
        float p[4];
#pragma unroll
        for (int ci = 0; ci < 4; ci++) p[ci] = scb[ci * SCBW + s];
        const float* vr = Vb + (size_t)(k0 + s) * 64 + dof;
        float vf[16];
#pragma unroll
        for (int i = 0; i < 4; i++) *(float4*)&vf[i * 4] = *(const float4*)&vr[i * 4];
#pragma unroll
        for (int dd = 0; dd < 16; dd++) {
            float vv = vf[dd];
            acc[0][dd] = fmaf(p[0], vv, acc[0][dd]);
            acc[1][dd] = fmaf(p[1], vv, acc[1][dd]);
            acc[2][dd] = fmaf(p[2], vv, acc[2][dd]);
            acc[3][dd] = fmaf(p[3], vv, acc[3][dd]);
        }
    }
#pragma unroll
    for (int o = 4; o <= 16; o <<= 1)
#pragma unroll
        for (int ci = 0; ci < 4; ci++)
#pragma unroll
            for (int dd = 0; dd < 16; dd++)
                acc[ci][dd] += __shfl_xor_sync(0xffffffffu, acc[ci][dd], o);

    if ((lane & 28) == 0) {
#pragma unroll
        for (int ci = 0; ci < 4; ci++)
#pragma unroll
            for (int dd = 0; dd < 16; dd++)
                osum[w][ci][dof + dd] = acc[ci][dd];
    }
    __syncthreads();

    {
        int ci = tid >> 6, d = tid & 63;
        float v = 0.f;
#pragma unroll
        for (int i = 0; i < 8; i++) v += osum[i][ci][d];
        float* dst = &g_clsp[((size_t)(h * 4 + ci) * NCHUNK + chunk) * 66];
        dst[2 + d] = v;
        if (d == 0) { dst[0] = gm[ci]; dst[1] = gs[ci]; }
    }

    // fused last-block combine
    __threadfence();
    __syncthreads();
    if (tid == 0) s_old = atomicAdd(&g_cnt[h], 1);
    __syncthreads();
    if (s_old == NCHUNK - 1) {
        int ci = tid >> 6, d = tid & 63;
        int hc = h * 4 + ci;
        const float* base = &g_clsp[(size_t)hc * NCHUNK * 66];
        float M = -INFINITY;
#pragma unroll
        for (int c = 0; c < NCHUNK; c++) M = fmaxf(M, base[c * 66]);
        float S = 0.f, A = 0.f;
#pragma unroll
        for (int c = 0; c < NCHUNK; c++) {
            float wgt = __expf(base[c * 66] - M);
            S = fmaf(base[c * 66 + 1], wgt, S);
            A = fmaf(base[c * 66 + 2 + d], wgt, A);
        }
        g_af[(size_t)ci * 512 + h * 64 + d] = __float2half(A / S);
    }
}

// ---------------------------------------------------------------------------
// Patch attention on tensor cores, band-reduced (unchanged from R15)
// ---------------------------------------------------------------------------
#define PST 72
#define SQ_E (64 * PST)
#define SK_E (144 * PST)
#define PATCH_SMEM ((SQ_E + 2 * SK_E) * 2 + 128 * 4 + 128 * 4 + 4 * 16 * 66 * 4)

__launch_bounds__(256)
__global__ void patch_attn_kernel() {
    __half* sQ = (__half*)dynsm;
    __half* sK = sQ + SQ_E;
    __half* sV = sK + SK_E;
    float* hm = (float*)(dynsm + (SQ_E + 2 * SK_E) * 2);
    float* hs = hm + 128;
    float* redb = hs + 128;

    int h = blockIdx.y;
    int l0 = blockIdx.x * 64;
    int tid = threadIdx.x;

    const float* Qb = &g_qkv[(size_t)h * S_TOT * 64];
    const float* Kb = &g_qkv[(size_t)(8 + h) * S_TOT * 64];
    const float* Vb = &g_qkv[(size_t)(16 + h) * S_TOT * 64];

    for (int i = tid; i < 64 * 8; i += 256) {
        int r = i >> 3, c8 = (i & 7) * 8;
        const float* src = &Qb[(size_t)(NUM_CLS + l0 + r) * 64 + c8];
        float4 a = *(const float4*)src;
        float4 b = *(const float4*)(src + 4);
        uint4 pk = make_uint4(packf16(a.x * 0.125f, a.y * 0.125f),
                              packf16(a.z * 0.125f, a.w * 0.125f),
                              packf16(b.x * 0.125f, b.y * 0.125f),
                              packf16(b.z * 0.125f, b.w * 0.125f));
        *(uint4*)&sQ[r * PST + c8] = pk;
    }
    for (int i = tid; i < 144 * 8; i += 256) {
        int r = i >> 3, c8 = (i & 7) * 8;
        float4 ka = make_float4(0.f, 0.f, 0.f, 0.f), kb = ka, va = ka, vb = ka;
        if (r < 128) {
            int kp = l0 - WIN + r;
            if (kp >= 0 && kp < L_PAT) {
                const float* ks = &Kb[(size_t)(NUM_CLS + kp) * 64 + c8];
                const float* vs = &Vb[(size_t)(NUM_CLS + kp) * 64 + c8];
                ka = *(const float4*)ks; kb = *(const float4*)(ks + 4);
                va = *(const float4*)vs; vb = *(const float4*)(vs + 4);
            }
        } else if (r < 132) {
            const float* ks = &Kb[(size_t)(r - 128) * 64 + c8];
            const float* vs = &Vb[(size_t)(r - 128) * 64 + c8];
            ka = *(const float4*)ks; kb = *(const float4*)(ks + 4);
            va = *(const float4*)vs; vb = *(const float4*)(vs + 4);
        }
        *(uint4*)&sK[r * PST + c8] = make_uint4(packf16(ka.x, ka.y), packf16(ka.z, ka.w),
                                                packf16(kb.x, kb.y), packf16(kb.z, kb.w));
        *(uint4*)&sV[r * PST + c8] = make_uint4(packf16(va.x, va.y), packf16(va.z, va.w),
                                                packf16(vb.x, vb.y), packf16(vb.z, vb.w));
    }
    __syncthreads();

    const int wid = tid >> 5;
    const int lane = tid & 31;
    const int wm = (wid >> 1) * 16;
    const int wh = wid & 1;
    const int lrow = lane & 15;
    const int lcol = (lane >> 4) * 8;
    const int gid = lane >> 2;
    const int tig = lane & 3;

    const uint32_t sQb = smem_u32(sQ);
    const uint32_t sKb = smem_u32(sK);
    const uint32_t sVb = smem_u32(sV);

    int rbase[3];
#pragma unroll
    for (int ti = 0; ti < 3; ti++) {
        int t = wh * 3 + ti;
        rbase[ti] = (t < 5) ? (wm + t * 16) : 128;
    }

    float sf[3][2][4];
#pragma unroll
    for (int g = 0; g < 3; g++)
#pragma unroll
        for (int s = 0; s < 2; s++)
#pragma unroll
            for (int r = 0; r < 4; r++) sf[g][s][r] = 0.f;

#pragma unroll
    for (int kt = 0; kt < 4; kt++) {
        uint32_t af[4];
        ldm_x4(af, sQb + ((wm + lrow) * PST + kt * 16 + lcol) * 2);
#pragma unroll
        for (int g = 0; g < 3; g++) {
            uint32_t bf[4];
            ldm_x4(bf, sKb + ((rbase[g] + lrow) * PST + kt * 16 + lcol) * 2);
            mma_h(sf[g][0], af, bf[0], bf[2]);
            mma_h(sf[g][1], af, bf[1], bf[3]);
        }
    }

    const int row0 = wm + gid;
    const int row1 = row0 + 8;
    float mx0 = -INFINITY, mx1 = -INFINITY;
#pragma unroll
    for (int g = 0; g < 3; g++) {
        int t = wh * 3 + g;
#pragma unroll
        for (int s = 0; s < 2; s++)
#pragma unroll
            for (int j = 0; j < 2; j++) {
                int cc = s * 8 + tig * 2 + j;
                bool v0, v1;
                if (t < 5) {
                    int r = wm + t * 16 + cc;
                    int pos = l0 - WIN + r;
                    bool bok = (pos >= 0) && (pos < L_PAT);
                    v0 = bok && (r >= row0) && (r <= row0 + 64);
                    v1 = bok && (r >= row1) && (r <= row1 + 64);
                } else {
                    v0 = v1 = (cc < 4);
                }
                float a0 = v0 ? sf[g][s][j] : -1e30f;
                float a1 = v1 ? sf[g][s][j + 2] : -1e30f;
                sf[g][s][j] = a0;
                sf[g][s][j + 2] = a1;
                mx0 = fmaxf(mx0, a0);
                mx1 = fmaxf(mx1, a1);
            }
    }
    mx0 = fmaxf(mx0, __shfl_xor_sync(0xffffffffu, mx0, 1));
    mx0 = fmaxf(mx0, __shfl_xor_sync(0xffffffffu, mx0, 2));
    mx1 = fmaxf(mx1, __shfl_xor_sync(0xffffffffu, mx1, 1));
    mx1 = fmaxf(mx1, __shfl_xor_sync(0xffffffffu, mx1, 2));
    if (tig == 0) {
        hm[row0 * 2 + wh] = mx0;
        hm[row1 * 2 + wh] = mx1;
    }
    __syncthreads();
    float M0 = fmaxf(hm[row0 * 2], hm[row0 * 2 + 1]);
    float M1 = fmaxf(hm[row1 * 2], hm[row1 * 2 + 1]);

    float sum0 = 0.f, sum1 = 0.f;
#pragma unroll
    for (int g = 0; g < 3; g++)
#pragma unroll
        for (int s = 0; s < 2; s++) {
            float p0 = fexp(sf[g][s][0] - M0);
            float p1 = fexp(sf[g][s][1] - M0);
            float p2 = fexp(sf[g][s][2] - M1);
            float p3 = fexp(sf[g][s][3] - M1);
            sf[g][s][0] = p0; sf[g][s][1] = p1;
            sf[g][s][2] = p2; sf[g][s][3] = p3;
            sum0 += p0 + p1;
            sum1 += p2 + p3;
        }
    sum0 += __shfl_xor_sync(0xffffffffu, sum0, 1);
    sum0 += __shfl_xor_sync(0xffffffffu, sum0, 2);
    sum1 += __shfl_xor_sync(0xffffffffu, sum1, 1);
    sum1 += __shfl_xor_sync(0xffffffffu, sum1, 2);
    if (tig == 0) {
        hs[row0 * 2 + wh] = sum0;
        hs[row1 * 2 + wh] = sum1;
    }
    __syncthreads();
    float inv0 = 1.0f / (hs[row0 * 2] + hs[row0 * 2 + 1]);
    float inv1 = 1.0f / (hs[row1 * 2] + hs[row1 * 2 + 1]);

    uint32_t PhA[3][4];
#pragma unroll
    for (int kt = 0; kt < 3; kt++) {
#pragma unroll
        for (int s = 0; s < 2; s++) {
            PhA[kt][0 + s * 2] = packf16(sf[kt][s][0] * inv0, sf[kt][s][1] * inv0);
            PhA[kt][1 + s * 2] = packf16(sf[kt][s][2] * inv1, sf[kt][s][3] * inv1);
        }
    }

    float of[8][4];
#pragma unroll
    for (int i = 0; i < 8; i++)
#pragma unroll
        for (int r = 0; r < 4; r++) of[i][r] = 0.f;

#pragma unroll
    for (int dt2 = 0; dt2 < 4; dt2++) {
#pragma unroll
        for (int kt = 0; kt < 3; kt++) {
            uint32_t vb[4];
            ldm_x4t(vb, sVb + ((rbase[kt] + lrow) * PST + dt2 * 16 + lcol) * 2);
            mma_h(of[2 * dt2 + 0], PhA[kt], vb[0], vb[1]);
            mma_h(of[2 * dt2 + 1], PhA[kt], vb[2], vb[3]);
        }
    }

    float* rb = redb + (wm >> 4) * 16 * 66;
    if (wh == 1) {
#pragma unroll
        for (int dt = 0; dt < 8; dt++) {
            int d = dt * 8 + tig * 2;
            *(float2*)&rb[gid * 66 + d] = make_float2(of[dt][0], of[dt][1]);
            *(float2*)&rb[(gid + 8) * 66 + d] = make_float2(of[dt][2], of[dt][3]);
        }
    }
    __syncthreads();
    if (wh == 0) {
#pragma unroll
        for (int dt = 0; dt < 8; dt++) {
            int d = dt * 8 + tig * 2;
            float2 r0 = *(float2*)&rb[gid * 66 + d];
            float2 r1 = *(float2*)&rb[(gid + 8) * 66 + d];
            int grow0 = NUM_CLS + l0 + row0;
            int grow1 = NUM_CLS + l0 + row1;
            *(uint32_t*)&g_af[(size_t)grow0 * 512 + h * 64 + d] =
                packf16(of[dt][0] + r0.x, of[dt][1] + r0.y);
            *(uint32_t*)&g_af[(size_t)grow1 * 512 + h * 64 + d] =
                packf16(of[dt][2] + r1.x, of[dt][3] + r1.y);
        }
    }
}

// ---------------------------------------------------------------------------
extern "C" void kernel_launch(void* const* d_in, const int* in_sizes, int n_in,
                              void* d_out, int out_size) {
    const float* x      = (const float*)d_in[0];
    const float* coords = (const float*)d_in[1];
    const float* w_qkv  = (const float*)d_in[2];
    const float* b_qkv  = (const float*)d_in[3];
    const float* w_out  = (const float*)d_in[4];
    const float* b_out  = (const float*)d_in[5];
    float* out = (float*)d_out;

    __half *xf, *af, *wqf, *wof;
    cudaGetSymbolAddress((void**)&xf, g_xf);
    cudaGetSymbolAddress((void**)&af, g_af);
    cudaGetSymbolAddress((void**)&wqf, g_wqf);
    cudaGetSymbolAddress((void**)&wof, g_wof);

    cudaFuncSetAttribute(gemm_f16<0>, cudaFuncAttributeMaxDynamicSharedMemorySize, GEMM_SMEM);
    cudaFuncSetAttribute(gemm_f16<1>, cudaFuncAttributeMaxDynamicSharedMemorySize, GEMM_SMEM);
    cudaFuncSetAttribute(patch_attn_kernel, cudaFuncAttributeMaxDynamicSharedMemorySize, PATCH_SMEM);

    // 1. fused prep
    prep_kernel<<<NB_PREP, 256>>>(x, w_qkv, w_out, coords);

    // 2. QKV GEMM (rope fused) -> g_qkv scatter
    {
        dim3 grid(1536 / 128, (S_TOT + 127) / 128);
        gemm_f16<1><<<grid, 256, GEMM_SMEM>>>(xf, wqf, b_qkv, nullptr, S_TOT, 0);
    }
    // 3. CLS attention (combine fused into last block)
    {
        dim3 grid(8, NCHUNK);
        cls_part_kernel<<<grid, 256>>>();
    }
    // 4. Patch attention (band-reduced)
    {
        dim3 grid(L_PAT / 64, H_NUM);
        patch_attn_kernel<<<grid, 256, PATCH_SMEM>>>();
    }
    // 5. out projection
    {
        dim3 grid(512 / 128, (S_TOT + 127) / 128);
        gemm_f16<0><<<grid, 256, GEMM_SMEM>>>(af, wof, b_out, out, S_TOT, 512);
    }
}